// round 2
// baseline (speedup 1.0000x reference)
#include <cuda_runtime.h>
#include <math.h>

#define NN   50000
#define EE   200000
#define BB   2048
#define ATT  16
#define ETT  4
#define H    32
#define LL   3
#define LAT  64
#define HLD  256
#define FEAT 245
#define MAXN 50.0f
#define GPB  8

// ---------------- scratch (device globals; no allocation allowed) ----------------
__device__ float g_h[NN * H];
__device__ float g_hnew[NN * H];
__device__ float g_P[NN * 5 * H];     // 32 MB: per-node precomputed h@W_t (t=0..3) and h@Bmat (t=4)
__device__ float g_agg[NN * H];
__device__ float g_deg[NN];
__device__ float g_invdeg[NN];
__device__ float g_cnt[BB];
__device__ float g_feats[BB * FEAT];
__device__ float g_poolsum[BB * H];
__device__ float g_poolmax[BB * H];
__device__ float g_bnsum[H];
__device__ float g_bnsq[H];
__device__ float g_bnA[H];
__device__ float g_bnB[H];

// float atomic max via monotone int/uint mapping
__device__ __forceinline__ void atomicMaxFloat(float* addr, float v) {
    if (v >= 0.f) atomicMax((int*)addr, __float_as_int(v));
    else          atomicMin((unsigned int*)addr, __float_as_uint(v));
}

// ---------------- zero / init ----------------
__global__ void k_zero_global() {
    int i = blockIdx.x * blockDim.x + threadIdx.x;
    if (i < BB * FEAT) g_feats[i] = 0.f;
    if (i < NN)        g_deg[i] = 0.f;
    if (i < BB)        g_cnt[i] = 0.f;
}

__global__ void k_zero_layer() {
    int i = blockIdx.x * blockDim.x + threadIdx.x;
    if (i < NN * H) g_agg[i] = 0.f;
    if (i < BB * H) { g_poolsum[i] = 0.f; g_poolmax[i] = -INFINITY; }
    if (i < H)      { g_bnsum[i] = 0.f; g_bnsq[i] = 0.f; }
}

// ---------------- graph-level stats ----------------
// in-degree (by tgt) + per-graph edge-type counts (by batch[src])
__global__ void k_stats_edges(const int* __restrict__ ei, const float* __restrict__ et,
                              const int* __restrict__ batch) {
    int e = blockIdx.x * blockDim.x + threadIdx.x;
    if (e >= EE) return;
    int s = ei[e];
    int t = ei[EE + e];
    atomicAdd(&g_deg[t], 1.f);
    int g = batch[s];
    const float inv = 1.f / MAXN;
#pragma unroll
    for (int j = 0; j < ETT; j++)
        atomicAdd(&g_feats[g * FEAT + 1 + j], et[e * ETT + j] * inv);
}

__global__ void k_invdeg() {
    int n = blockIdx.x * blockDim.x + threadIdx.x;
    if (n < NN) g_invdeg[n] = 1.f / fmaxf(g_deg[n], 1.f);
}

// x pools: raw sum into mean slots (finished later), max into max slots, node count
__global__ void k_xpool(const float* __restrict__ x, const int* __restrict__ batch) {
    int i = blockIdx.x * blockDim.x + threadIdx.x;
    if (i >= NN * ATT) return;
    int n = i / ATT, c = i % ATT;
    int g = batch[n];
    float v = x[i];
    atomicAdd(&g_feats[g * FEAT + 21 + c], v);
    atomicMaxFloat(&g_feats[g * FEAT + 37 + c], v);   // x >= 0, zero-init is safe
    if (c == 0) atomicAdd(&g_cnt[g], 1.f);
}

__global__ void k_finish_x() {
    int i = blockIdx.x * blockDim.x + threadIdx.x;
    if (i >= BB * ATT) return;
    int g = i / ATT, c = i % ATT;
    float cnt = g_cnt[g];
    float sum = g_feats[g * FEAT + 21 + c];
    g_feats[g * FEAT + 5 + c]  = sum / MAXN;
    g_feats[g * FEAT + 21 + c] = sum / fmaxf(cnt, 1.f);
    if (cnt <= 0.f) g_feats[g * FEAT + 37 + c] = 0.f;
    if (c == 0) g_feats[g * FEAT] = cnt / MAXN;
}

// ---------------- initial node MLP: h = relu(x@W0+b0)@W1+b1 (warp per node) ----------------
__global__ void k_init_mlp(const float* __restrict__ x,
                           const float* __restrict__ w0, const float* __restrict__ b0,
                           const float* __restrict__ w1, const float* __restrict__ b1) {
    __shared__ float sw0[ATT * H], sw1[H * H], sb0[H], sb1[H];
    int tid = threadIdx.x;
    for (int i = tid; i < ATT * H; i += blockDim.x) sw0[i] = w0[i];
    for (int i = tid; i < H * H;  i += blockDim.x) sw1[i] = w1[i];
    if (tid < H) { sb0[tid] = b0[tid]; sb1[tid] = b1[tid]; }
    __syncthreads();
    int warp = (blockIdx.x * blockDim.x + tid) >> 5;
    int lane = tid & 31;
    if (warp >= NN) return;
    float xa = (lane < ATT) ? x[warp * ATT + lane] : 0.f;
    float t = sb0[lane];
#pragma unroll
    for (int a = 0; a < ATT; a++)
        t += __shfl_sync(0xffffffffu, xa, a) * sw0[a * H + lane];
    t = fmaxf(t, 0.f);
    float hv = sb1[lane];
#pragma unroll
    for (int k = 0; k < H; k++)
        hv += __shfl_sync(0xffffffffu, t, k) * sw1[k * H + lane];
    g_h[warp * H + lane] = hv;
}

// ---------------- per-node precompute: P[n,t,:] = h[n] @ W_t (warp per node) ----------------
__global__ void k_precompute(const float* __restrict__ enw, const float* __restrict__ enb, int l) {
    __shared__ float sW[5 * H * H];   // 20 KB: 4 edge-type matrices + bias matrix
    int tid = threadIdx.x;
    for (int i = tid; i < ETT * H * H; i += blockDim.x) sW[i] = enw[(l * ETT) * H * H + i];
    for (int i = tid; i < H * H; i += blockDim.x)       sW[4 * H * H + i] = enb[l * H * H + i];
    __syncthreads();
    int warp = (blockIdx.x * blockDim.x + tid) >> 5;
    int lane = tid & 31;
    if (warp >= NN) return;
    float hv = g_h[warp * H + lane];
    float acc0 = 0.f, acc1 = 0.f, acc2 = 0.f, acc3 = 0.f, acc4 = 0.f;
#pragma unroll
    for (int hh = 0; hh < H; hh++) {
        float hb = __shfl_sync(0xffffffffu, hv, hh);
        acc0 += hb * sW[0 * H * H + hh * H + lane];
        acc1 += hb * sW[1 * H * H + hh * H + lane];
        acc2 += hb * sW[2 * H * H + hh * H + lane];
        acc3 += hb * sW[3 * H * H + hh * H + lane];
        acc4 += hb * sW[4 * H * H + hh * H + lane];
    }
    float* Pr = &g_P[warp * 5 * H];
    Pr[0 * H + lane] = acc0;
    Pr[1 * H + lane] = acc1;
    Pr[2 * H + lane] = acc2;
    Pr[3 * H + lane] = acc3;
    Pr[4 * H + lane] = acc4;
}

// ---------------- edge pass: msg = Σ_t et[e,t]·P[src,t,:] + P[src,4,:] → scatter-add (warp per edge) ----------------
__global__ void k_edge(const int* __restrict__ ei, const float* __restrict__ et) {
    int gid = blockIdx.x * blockDim.x + threadIdx.x;
    int e = gid >> 5;
    int lane = gid & 31;
    if (e >= EE) return;
    int s = ei[e];
    int t = ei[EE + e];
    float etv = (lane < ETT) ? et[e * ETT + lane] : 0.f;
    const float* __restrict__ Pr = &g_P[s * 5 * H];
    float acc = Pr[4 * H + lane];
#pragma unroll
    for (int j = 0; j < ETT; j++)
        acc += __shfl_sync(0xffffffffu, etv, j) * Pr[j * H + lane];
    atomicAdd(&g_agg[t * H + lane], acc);   // lanes hit one 128B line: coalesced RED
}

// ---------------- node update: new_x = h@root + agg*invdeg + b; pools; h' = relu(new_x)+h; BN stats ----------------
__global__ void k_update(const float* __restrict__ rw, const float* __restrict__ cb,
                         const int* __restrict__ batch, int l) {
    __shared__ float srw[H * H];
    __shared__ float scb[H], ssum[H], ssq[H];
    int tid = threadIdx.x;
    for (int i = tid; i < H * H; i += blockDim.x) srw[i] = rw[l * H * H + i];
    if (tid < H) { scb[tid] = cb[l * H + tid]; ssum[tid] = 0.f; ssq[tid] = 0.f; }
    __syncthreads();
    int warp = (blockIdx.x * blockDim.x + tid) >> 5;
    int lane = tid & 31;
    float lsum = 0.f, lsq = 0.f;
    if (warp < NN) {
        float hv = g_h[warp * H + lane];
        float nx = scb[lane] + g_agg[warp * H + lane] * g_invdeg[warp];
#pragma unroll
        for (int hh = 0; hh < H; hh++)
            nx += __shfl_sync(0xffffffffu, hv, hh) * srw[hh * H + lane];
        int g = batch[warp];
        atomicAdd(&g_poolsum[g * H + lane], nx);
        atomicMaxFloat(&g_poolmax[g * H + lane], nx);
        float hp = fmaxf(nx, 0.f) + hv;
        g_hnew[warp * H + lane] = hp;
        lsum = hp; lsq = hp * hp;
    }
    atomicAdd(&ssum[lane], lsum);
    atomicAdd(&ssq[lane], lsq);
    __syncthreads();
    if (tid < H) {
        atomicAdd(&g_bnsum[tid], ssum[tid]);
        atomicAdd(&g_bnsq[tid], ssq[tid]);
    }
}

__global__ void k_pool_finish(int l) {
    int i = blockIdx.x * blockDim.x + threadIdx.x;
    if (i >= BB * H) return;
    int g = i / H, k = i % H;
    float cnt = g_cnt[g];
    float m  = g_poolsum[i] / fmaxf(cnt, 1.f);
    float mx = (cnt > 0.f) ? g_poolmax[i] : 0.f;
    g_feats[g * FEAT + 53 + l * 2 * H + k]     = m;
    g_feats[g * FEAT + 53 + l * 2 * H + H + k] = mx;
}

__global__ void k_bn_finish(const float* __restrict__ gamma, const float* __restrict__ beta, int l) {
    int k = threadIdx.x;
    if (k >= H) return;
    float mu  = g_bnsum[k] / (float)NN;
    float var = g_bnsq[k] / (float)NN - mu * mu;
    float A = gamma[l * H + k] * rsqrtf(var + 1e-5f);
    g_bnA[k] = A;
    g_bnB[k] = beta[l * H + k] - mu * A;
}

__global__ void k_bn_apply() {
    int i = blockIdx.x * blockDim.x + threadIdx.x;
    if (i >= NN * H) return;
    int k = i & (H - 1);
    g_h[i] = g_hnew[i] * g_bnA[k] + g_bnB[k];
}

// ---------------- final MLP: feats[B,245]@W0 relu @W1 (8 graphs per block) ----------------
__global__ void k_final(const float* __restrict__ w0, const float* __restrict__ b0,
                        const float* __restrict__ w1, const float* __restrict__ b1,
                        float* __restrict__ out) {
    __shared__ float sf[GPB * FEAT];
    __shared__ float st[GPB * HLD];
    int tid = threadIdx.x;
    int g0 = blockIdx.x * GPB;
    for (int i = tid; i < GPB * FEAT; i += blockDim.x) {
        int gg = i / FEAT;
        sf[i] = g_feats[(g0 + gg) * FEAT + (i - gg * FEAT)];
    }
    __syncthreads();
    // phase 1: column tid of hidden layer, 8 graphs
    {
        float acc[GPB];
        float bb = b0[tid];
#pragma unroll
        for (int gg = 0; gg < GPB; gg++) acc[gg] = bb;
        for (int i = 0; i < FEAT; i++) {
            float w = w0[i * HLD + tid];
#pragma unroll
            for (int gg = 0; gg < GPB; gg++) acc[gg] += sf[gg * FEAT + i] * w;
        }
#pragma unroll
        for (int gg = 0; gg < GPB; gg++) st[gg * HLD + tid] = fmaxf(acc[gg], 0.f);
    }
    __syncthreads();
    // phase 2: 256 threads = 2 halves × 128 output cols, 4 graphs each
    {
        int col = tid & 127;
        int gbase = (tid >> 7) * 4;
        float bb = b1[col];
        float acc[4];
#pragma unroll
        for (int q = 0; q < 4; q++) acc[q] = bb;
        for (int i = 0; i < HLD; i++) {
            float w = w1[i * 2 * LAT + col];
#pragma unroll
            for (int q = 0; q < 4; q++) acc[q] += st[(gbase + q) * HLD + i] * w;
        }
#pragma unroll
        for (int q = 0; q < 4; q++) {
            int g = g0 + gbase + q;
            if (col < LAT) out[g * LAT + col] = acc[q];
            else           out[BB * LAT + g * LAT + (col - LAT)] = acc[q];
        }
    }
}

// ---------------- launch ----------------
extern "C" void kernel_launch(void* const* d_in, const int* in_sizes, int n_in,
                              void* d_out, int out_size) {
    const float* x      = (const float*)d_in[0];
    const int*   ei     = (const int*)  d_in[1];
    const float* et     = (const float*)d_in[2];
    const int*   batch  = (const int*)  d_in[3];
    const float* mlp0_w = (const float*)d_in[4];
    const float* mlp0_b = (const float*)d_in[5];
    const float* mlp1_w = (const float*)d_in[6];
    const float* mlp1_b = (const float*)d_in[7];
    const float* enw    = (const float*)d_in[8];
    const float* enb    = (const float*)d_in[9];
    const float* rw     = (const float*)d_in[10];
    const float* cb     = (const float*)d_in[11];
    const float* gamma  = (const float*)d_in[12];
    const float* beta   = (const float*)d_in[13];
    const float* f0w    = (const float*)d_in[14];
    const float* f0b    = (const float*)d_in[15];
    const float* f1w    = (const float*)d_in[16];
    const float* f1b    = (const float*)d_in[17];
    float* out = (float*)d_out;

    k_zero_global<<<(BB * FEAT + 255) / 256, 256>>>();
    k_stats_edges<<<(EE + 255) / 256, 256>>>(ei, et, batch);
    k_xpool<<<(NN * ATT + 255) / 256, 256>>>(x, batch);
    k_invdeg<<<(NN + 255) / 256, 256>>>();
    k_finish_x<<<(BB * ATT + 255) / 256, 256>>>();
    k_init_mlp<<<(NN * 32 + 255) / 256, 256>>>(x, mlp0_w, mlp0_b, mlp1_w, mlp1_b);

    for (int l = 0; l < LL; l++) {
        k_zero_layer<<<(NN * H + 255) / 256, 256>>>();
        k_precompute<<<(NN * 32 + 255) / 256, 256>>>(enw, enb, l);
        k_edge<<<(EE * 32 + 255) / 256, 256>>>(ei, et);
        k_update<<<(NN * 32 + 255) / 256, 256>>>(rw, cb, batch, l);
        k_pool_finish<<<(BB * H + 255) / 256, 256>>>(l);
        k_bn_finish<<<1, 32>>>(gamma, beta, l);
        k_bn_apply<<<(NN * H + 255) / 256, 256>>>();
    }

    k_final<<<BB / GPB, 256>>>(f0w, f0b, f1w, f1b, out);
}

// round 3
// speedup vs baseline: 1.1698x; 1.1698x over previous
#include <cuda_runtime.h>
#include <math.h>

#define NN   50000
#define EE   200000
#define BB   2048
#define ATT  16
#define ETT  4
#define H    32
#define LL   3
#define LAT  64
#define HLD  256
#define FEAT 245
#define MAXN 50.0f
#define GPB  8
#define NBU  592   // grid-stride blocks for k_update

// ---------------- scratch (device globals; no allocation allowed) ----------------
__device__ float g_h[NN * H];            // current (normalized) node features
__device__ float g_hnew[NN * H];         // pre-BN features (relu(nx)+h)
__device__ float g_P[NN * 5 * H];        // per-node h@W_t (t=0..3) and h@Bmat (t=4)
__device__ float g_hr[NN * H];           // per-node h@root_w
__device__ float g_agg[NN * H];
__device__ float g_deg[NN];
__device__ float g_invdeg[NN];
__device__ float g_cnt[BB];
__device__ float g_feats[BB * FEAT];
__device__ float g_poolsum[LL * BB * H];
__device__ float g_poolmax[LL * BB * H];
__device__ float g_bnpartS[NBU * H];
__device__ float g_bnpartQ[NBU * H];
__device__ float g_bnA[LL * H];
__device__ float g_bnB[LL * H];

// float atomic max via monotone int/uint mapping
__device__ __forceinline__ void atomicMaxFloat(float* addr, float v) {
    if (v >= 0.f) atomicMax((int*)addr, __float_as_int(v));
    else          atomicMin((unsigned int*)addr, __float_as_uint(v));
}

// ---------------- one-time zero ----------------
__global__ void k_zero() {
    int i = blockIdx.x * blockDim.x + threadIdx.x;
    if (i < NN * H)      g_agg[i] = 0.f;
    if (i < BB * FEAT)   g_feats[i] = 0.f;
    if (i < NN)          g_deg[i] = 0.f;
    if (i < BB)          g_cnt[i] = 0.f;
    if (i < LL * BB * H) { g_poolsum[i] = 0.f; g_poolmax[i] = -INFINITY; }
}

// ---------------- fused edge stats + x pools ----------------
__global__ void k_stats(const int* __restrict__ ei, const float* __restrict__ et,
                        const float* __restrict__ x, const int* __restrict__ batch) {
    int i = blockIdx.x * blockDim.x + threadIdx.x;
    if (i < NN * ATT) {
        int n = i / ATT, c = i % ATT;
        int g = batch[n];
        float v = x[i];
        atomicAdd(&g_feats[g * FEAT + 21 + c], v);
        atomicMaxFloat(&g_feats[g * FEAT + 37 + c], v);   // x >= 0, zero-init safe
        if (c == 0) atomicAdd(&g_cnt[g], 1.f);
    }
    if (i < EE) {
        int s = ei[i];
        int t = ei[EE + i];
        atomicAdd(&g_deg[t], 1.f);
        int g = batch[s];
        const float inv = 1.f / MAXN;
#pragma unroll
        for (int j = 0; j < ETT; j++)
            atomicAdd(&g_feats[g * FEAT + 1 + j], et[i * ETT + j] * inv);
    }
}

// ---------------- fused invdeg + x-feature finish ----------------
__global__ void k_finish(void) {
    int i = blockIdx.x * blockDim.x + threadIdx.x;
    if (i < NN) g_invdeg[i] = 1.f / fmaxf(g_deg[i], 1.f);
    if (i < BB * ATT) {
        int g = i / ATT, c = i % ATT;
        float cnt = g_cnt[g];
        float sum = g_feats[g * FEAT + 21 + c];
        g_feats[g * FEAT + 5 + c]  = sum / MAXN;
        g_feats[g * FEAT + 21 + c] = sum / fmaxf(cnt, 1.f);
        if (cnt <= 0.f) g_feats[g * FEAT + 37 + c] = 0.f;
        if (c == 0) g_feats[g * FEAT] = cnt / MAXN;
    }
}

// ---------------- initial node MLP (warp per node) ----------------
__global__ void k_init_mlp(const float* __restrict__ x,
                           const float* __restrict__ w0, const float* __restrict__ b0,
                           const float* __restrict__ w1, const float* __restrict__ b1) {
    __shared__ float sw0[ATT * H], sw1[H * H], sb0[H], sb1[H];
    int tid = threadIdx.x;
    for (int i = tid; i < ATT * H; i += blockDim.x) sw0[i] = w0[i];
    for (int i = tid; i < H * H;  i += blockDim.x) sw1[i] = w1[i];
    if (tid < H) { sb0[tid] = b0[tid]; sb1[tid] = b1[tid]; }
    __syncthreads();
    int warp = (blockIdx.x * blockDim.x + tid) >> 5;
    int lane = tid & 31;
    if (warp >= NN) return;
    float xa = (lane < ATT) ? x[warp * ATT + lane] : 0.f;
    float t = sb0[lane];
#pragma unroll
    for (int a = 0; a < ATT; a++)
        t += __shfl_sync(0xffffffffu, xa, a) * sw0[a * H + lane];
    t = fmaxf(t, 0.f);
    float hv = sb1[lane];
#pragma unroll
    for (int k = 0; k < H; k++)
        hv += __shfl_sync(0xffffffffu, t, k) * sw1[k * H + lane];
    g_h[warp * H + lane] = hv;
}

// ---------------- precompute GEMM: P[n,t,:], hr[n,:]; applies BN affine of previous layer
//                  4 nodes per warp so one weight LDS feeds 4 nodes ----------------
__global__ void k_precompute(const float* __restrict__ enw, const float* __restrict__ enb,
                             const float* __restrict__ rw, int l) {
    __shared__ float sW[6 * H * H];   // 24 KB: 4 edge-type mats + bias mat + root mat
    int tid = threadIdx.x;
    for (int i = tid; i < 5 * H * H; i += blockDim.x) {
        int t = i >> 10, rest = i & 1023;
        sW[i] = (t < 4) ? enw[(l * ETT + t) * H * H + rest] : enb[l * H * H + rest];
    }
    for (int i = tid; i < H * H; i += blockDim.x)
        sW[5 * H * H + i] = rw[l * H * H + i];
    __syncthreads();

    int warp = (blockIdx.x * blockDim.x + tid) >> 5;
    int lane = tid & 31;
    int nb = warp * 4;
    if (nb >= NN) return;

    float bnA = 0.f, bnB = 0.f;
    if (l > 0) { bnA = g_bnA[(l - 1) * H + lane]; bnB = g_bnB[(l - 1) * H + lane]; }

    float hv[4];
#pragma unroll
    for (int j = 0; j < 4; j++) {
        int n = nb + j;
        if (n < NN) {
            float v;
            if (l == 0) v = g_h[n * H + lane];
            else { v = fmaf(g_hnew[n * H + lane], bnA, bnB); g_h[n * H + lane] = v; }
            hv[j] = v;
        } else hv[j] = 0.f;
    }

    float a0[4] = {0,0,0,0}, a1[4] = {0,0,0,0}, a2[4] = {0,0,0,0};
    float a3[4] = {0,0,0,0}, a4[4] = {0,0,0,0}, a5[4] = {0,0,0,0};
#pragma unroll
    for (int hh = 0; hh < H; hh++) {
        float w0 = sW[0 * 1024 + hh * H + lane];
        float w1 = sW[1 * 1024 + hh * H + lane];
        float w2 = sW[2 * 1024 + hh * H + lane];
        float w3 = sW[3 * 1024 + hh * H + lane];
        float w4 = sW[4 * 1024 + hh * H + lane];
        float w5 = sW[5 * 1024 + hh * H + lane];
#pragma unroll
        for (int j = 0; j < 4; j++) {
            float hb = __shfl_sync(0xffffffffu, hv[j], hh);
            a0[j] = fmaf(hb, w0, a0[j]);
            a1[j] = fmaf(hb, w1, a1[j]);
            a2[j] = fmaf(hb, w2, a2[j]);
            a3[j] = fmaf(hb, w3, a3[j]);
            a4[j] = fmaf(hb, w4, a4[j]);
            a5[j] = fmaf(hb, w5, a5[j]);
        }
    }
#pragma unroll
    for (int j = 0; j < 4; j++) {
        int n = nb + j;
        if (n >= NN) break;
        float* Pr = &g_P[n * 5 * H];
        Pr[0 * H + lane] = a0[j];
        Pr[1 * H + lane] = a1[j];
        Pr[2 * H + lane] = a2[j];
        Pr[3 * H + lane] = a3[j];
        Pr[4 * H + lane] = a4[j];
        g_hr[n * H + lane] = a5[j];
    }
}

// ---------------- edge pass: msg = Σ_t et·P[src,t,:] + P[src,4,:] → scatter-add ----------------
__global__ void k_edge(const int* __restrict__ ei, const float* __restrict__ et) {
    int gid = blockIdx.x * blockDim.x + threadIdx.x;
    int e = gid >> 5;
    int lane = gid & 31;
    if (e >= EE) return;
    int s = ei[e];
    int t = ei[EE + e];
    float etv = (lane < ETT) ? et[e * ETT + lane] : 0.f;
    const float* __restrict__ Pr = &g_P[s * 5 * H];
    float acc = Pr[4 * H + lane];
#pragma unroll
    for (int j = 0; j < ETT; j++)
        acc += __shfl_sync(0xffffffffu, etv, j) * Pr[j * H + lane];
    atomicAdd(&g_agg[t * H + lane], acc);   // lanes hit one 128B line: coalesced RED
}

// ---------------- node update (grid-stride streaming): nx = hr + agg*invdeg + b;
//                  pools; hnew = relu(nx)+h; BN partials; re-zero agg ----------------
__global__ void k_update(const float* __restrict__ cb, const int* __restrict__ batch, int l) {
    __shared__ float ssum[H], ssq[H];
    int tid = threadIdx.x;
    int lane = tid & 31;
    if (tid < H) { ssum[tid] = 0.f; ssq[tid] = 0.f; }
    __syncthreads();
    float bias = cb[l * H + lane];     // i%32 is invariant per thread (strides are mult of 32)
    float lsum = 0.f, lsq = 0.f;
    float* psum = &g_poolsum[l * BB * H];
    float* pmax = &g_poolmax[l * BB * H];
    for (int i = blockIdx.x * blockDim.x + tid; i < NN * H; i += gridDim.x * blockDim.x) {
        int n = i >> 5;
        float hv = g_h[i];
        float nx = bias + g_agg[i] * g_invdeg[n] + g_hr[i];
        g_agg[i] = 0.f;                 // ready for next layer
        int g = batch[n];
        atomicAdd(&psum[g * H + lane], nx);
        atomicMaxFloat(&pmax[g * H + lane], nx);
        float hp = fmaxf(nx, 0.f) + hv;
        g_hnew[i] = hp;
        lsum += hp; lsq += hp * hp;
    }
    atomicAdd(&ssum[lane], lsum);
    atomicAdd(&ssq[lane], lsq);
    __syncthreads();
    if (tid < H) {
        g_bnpartS[blockIdx.x * H + tid] = ssum[tid];
        g_bnpartQ[blockIdx.x * H + tid] = ssq[tid];
    }
}

// ---------------- fused pool-finish + BN-finish ----------------
__global__ void k_post(const float* __restrict__ gamma, const float* __restrict__ beta, int l) {
    int i = blockIdx.x * blockDim.x + threadIdx.x;
    if (i < BB * H) {
        int g = i / H, k = i % H;
        float cnt = g_cnt[g];
        float m  = g_poolsum[l * BB * H + i] / fmaxf(cnt, 1.f);
        float mx = (cnt > 0.f) ? g_poolmax[l * BB * H + i] : 0.f;
        g_feats[g * FEAT + 53 + l * 2 * H + k]     = m;
        g_feats[g * FEAT + 53 + l * 2 * H + H + k] = mx;
    }
    if (i < H) {
        float s = 0.f, q = 0.f;
        for (int b = 0; b < NBU; b++) {
            s += g_bnpartS[b * H + i];
            q += g_bnpartQ[b * H + i];
        }
        float mu  = s / (float)NN;
        float var = q / (float)NN - mu * mu;
        float A = gamma[l * H + i] * rsqrtf(var + 1e-5f);
        g_bnA[l * H + i] = A;
        g_bnB[l * H + i] = beta[l * H + i] - mu * A;
    }
}

// ---------------- final MLP: feats[B,245]@W0 relu @W1 (8 graphs per block) ----------------
__global__ void k_final(const float* __restrict__ w0, const float* __restrict__ b0,
                        const float* __restrict__ w1, const float* __restrict__ b1,
                        float* __restrict__ out) {
    __shared__ float sf[GPB * FEAT];
    __shared__ float st[GPB * HLD];
    int tid = threadIdx.x;
    int g0 = blockIdx.x * GPB;
    for (int i = tid; i < GPB * FEAT; i += blockDim.x) {
        int gg = i / FEAT;
        sf[i] = g_feats[(g0 + gg) * FEAT + (i - gg * FEAT)];
    }
    __syncthreads();
    {
        float acc[GPB];
        float bb = b0[tid];
#pragma unroll
        for (int gg = 0; gg < GPB; gg++) acc[gg] = bb;
        for (int i = 0; i < FEAT; i++) {
            float w = w0[i * HLD + tid];
#pragma unroll
            for (int gg = 0; gg < GPB; gg++) acc[gg] = fmaf(sf[gg * FEAT + i], w, acc[gg]);
        }
#pragma unroll
        for (int gg = 0; gg < GPB; gg++) st[gg * HLD + tid] = fmaxf(acc[gg], 0.f);
    }
    __syncthreads();
    {
        int col = tid & 127;
        int gbase = (tid >> 7) * 4;
        float bb = b1[col];
        float acc[4];
#pragma unroll
        for (int q = 0; q < 4; q++) acc[q] = bb;
        for (int i = 0; i < HLD; i++) {
            float w = w1[i * 2 * LAT + col];
#pragma unroll
            for (int q = 0; q < 4; q++) acc[q] = fmaf(st[(gbase + q) * HLD + i], w, acc[q]);
        }
#pragma unroll
        for (int q = 0; q < 4; q++) {
            int g = g0 + gbase + q;
            if (col < LAT) out[g * LAT + col] = acc[q];
            else           out[BB * LAT + g * LAT + (col - LAT)] = acc[q];
        }
    }
}

// ---------------- launch ----------------
extern "C" void kernel_launch(void* const* d_in, const int* in_sizes, int n_in,
                              void* d_out, int out_size) {
    const float* x      = (const float*)d_in[0];
    const int*   ei     = (const int*)  d_in[1];
    const float* et     = (const float*)d_in[2];
    const int*   batch  = (const int*)  d_in[3];
    const float* mlp0_w = (const float*)d_in[4];
    const float* mlp0_b = (const float*)d_in[5];
    const float* mlp1_w = (const float*)d_in[6];
    const float* mlp1_b = (const float*)d_in[7];
    const float* enw    = (const float*)d_in[8];
    const float* enb    = (const float*)d_in[9];
    const float* rw     = (const float*)d_in[10];
    const float* cb     = (const float*)d_in[11];
    const float* gamma  = (const float*)d_in[12];
    const float* beta   = (const float*)d_in[13];
    const float* f0w    = (const float*)d_in[14];
    const float* f0b    = (const float*)d_in[15];
    const float* f1w    = (const float*)d_in[16];
    const float* f1b    = (const float*)d_in[17];
    float* out = (float*)d_out;

    k_zero<<<(NN * H + 255) / 256, 256>>>();
    k_stats<<<(NN * ATT + 255) / 256, 256>>>(ei, et, x, batch);
    k_finish<<<(NN + 255) / 256, 256>>>();
    k_init_mlp<<<(NN * 32 + 255) / 256, 256>>>(x, mlp0_w, mlp0_b, mlp1_w, mlp1_b);

    for (int l = 0; l < LL; l++) {
        k_precompute<<<(NN / 4 + 7) / 8, 256>>>(enw, enb, rw, l);   // 8 warps * 4 nodes per block
        k_edge<<<(EE * 32 + 255) / 256, 256>>>(ei, et);
        k_update<<<NBU, 256>>>(cb, batch, l);
        k_post<<<(BB * H + 255) / 256, 256>>>(gamma, beta, l);
    }

    k_final<<<BB / GPB, 256>>>(f0w, f0b, f1w, f1b, out);
}